// round 9
// baseline (speedup 1.0000x reference)
#include <cuda_runtime.h>
#include <cstdint>

using ull = unsigned long long;

static constexpr int D = 256, H = 512, NCLS = 10, TPTS = 8;
static constexpr int ROWS = 16, THREADS = 256;
static constexpr int STR = 20;                 // padded floats per transposed row (16 used)
// smem layout (floats)
static constexpr int OFF_YT  = 0;              // 256*20
static constexpr int OFF_YST = 256 * STR;      // 5120  (also GEMM2 reduction scratch)
static constexpr int OFF_HT  = OFF_YST + 256 * STR;   // 10240
static constexpr int OFF_KT  = OFF_HT + 512 * STR;    // 20480
static constexpr int KT_STRIDE = 256 * STR;    // 5120 floats per k-stage
static constexpr int SMEM_FLOATS = OFF_KT + 6 * KT_STRIDE;   // 51200
static constexpr int SMEM_BYTES  = SMEM_FLOATS * 4;          // 204800

__device__ __forceinline__ ull fma2(ull a, ull b, ull c) {
    ull d; asm("fma.rn.f32x2 %0, %1, %2, %3;" : "=l"(d) : "l"(a), "l"(b), "l"(c)); return d;
}
__device__ __forceinline__ ull add2(ull a, ull b) {
    ull d; asm("add.rn.f32x2 %0, %1, %2;" : "=l"(d) : "l"(a), "l"(b)); return d;
}
__device__ __forceinline__ ull pack2(float x) {
    ull r; asm("mov.b64 %0, {%1, %1};" : "=l"(r) : "f"(x)); return r;
}
__device__ __forceinline__ float2 u2f(ull v) {
    float2 r; asm("mov.b64 {%0, %1}, %2;" : "=f"(r.x), "=f"(r.y) : "l"(v)); return r;
}
__device__ __forceinline__ float tanhfast(float x) {
    float e = __expf(2.0f * x);
    return 1.0f - __fdividef(2.0f, e + 1.0f);
}

// one 8-k block: acts transposed rows (stride STR), weights preloaded in w[8]
// acc[pair p][col]: pair = rows (2p, 2p+1) packed as f32x2
__device__ __forceinline__ void g_block(const float* actT, const float2* w, ull (&acc)[8][2]) {
#pragma unroll
    for (int j = 0; j < 8; j++) {
        const float* row = actT + j * STR;
        ulonglong2 a01 = *(const ulonglong2*)(row);
        ulonglong2 a23 = *(const ulonglong2*)(row + 4);
        ulonglong2 a45 = *(const ulonglong2*)(row + 8);
        ulonglong2 a67 = *(const ulonglong2*)(row + 12);
        ull a[8] = {a01.x, a01.y, a23.x, a23.y, a45.x, a45.y, a67.x, a67.y};
        ull b0 = pack2(w[j].x), b1 = pack2(w[j].y);
#pragma unroll
        for (int p = 0; p < 8; p++) {
            acc[p][0] = fma2(a[p], b0, acc[p][0]);
            acc[p][1] = fma2(a[p], b1, acc[p][1]);
        }
    }
}

// generic pipelined GEMM inner loop: K = 256 k's, weights from gmem (row stride ws)
__device__ __forceinline__ void gemm_loop(const float* actT, const float* wp, int ws,
                                          ull (&acc)[8][2]) {
    float2 wA[8], wB[8];
#pragma unroll
    for (int j = 0; j < 8; j++) wA[j] = *(const float2*)(wp + j * ws);
#pragma unroll 1
    for (int kb = 0; kb < 32; kb += 2) {
        const float* wpn = wp + (kb + 1) * 8 * ws;
#pragma unroll
        for (int j = 0; j < 8; j++) wB[j] = *(const float2*)(wpn + j * ws);
        g_block(actT + kb * 8 * STR, wA, acc);
        if (kb + 2 < 32) {
            const float* wpn2 = wp + (kb + 2) * 8 * ws;
#pragma unroll
            for (int j = 0; j < 8; j++) wA[j] = *(const float2*)(wpn2 + j * ws);
        }
        g_block(actT + (kb + 1) * 8 * STR, wB, acc);
    }
}

// GEMM1: hT = tanh(actT^T @ W1 + b1), thread owns all 16 rows x cols (c0, c0+1)
__device__ __forceinline__ void gemm1(const float* actT, const float* W1g, float* hT,
                                      float2 b1v, int c0) {
    ull acc[8][2];
#pragma unroll
    for (int p = 0; p < 8; p++) { acc[p][0] = 0ULL; acc[p][1] = 0ULL; }
    gemm_loop(actT, W1g + c0, H, acc);
    float* h0 = hT + c0 * STR;
    float* h1 = hT + (c0 + 1) * STR;
#pragma unroll
    for (int q = 0; q < 4; q++) {
        float2 fa = u2f(acc[2 * q][0]), fb = u2f(acc[2 * q + 1][0]);
        float4 v;
        v.x = tanhfast(fa.x + b1v.x); v.y = tanhfast(fa.y + b1v.x);
        v.z = tanhfast(fb.x + b1v.x); v.w = tanhfast(fb.y + b1v.x);
        *(float4*)(h0 + 4 * q) = v;
        float2 ga = u2f(acc[2 * q][1]), gb = u2f(acc[2 * q + 1][1]);
        v.x = tanhfast(ga.x + b1v.y); v.y = tanhfast(ga.y + b1v.y);
        v.z = tanhfast(gb.x + b1v.y); v.w = tanhfast(gb.y + b1v.y);
        *(float4*)(h1 + 4 * q) = v;
    }
}

// GEMM2 (K split in half across thread halves): kdst = hT^T @ W2 + b2
// thread owns all 16 rows x cols (c2, c2+1) over its K-half; reduce via scratch.
__device__ __forceinline__ void gemm2(const float* hT, const float* W2g, float* scratch,
                                      float* kdst, ull b2p0, ull b2p1,
                                      int c2, int khalf, int tid) {
    ull acc[8][2];
#pragma unroll
    for (int p = 0; p < 8; p++) { acc[p][0] = 0ULL; acc[p][1] = 0ULL; }
    gemm_loop(hT + khalf * 256 * STR, W2g + (size_t)khalf * 256 * D + c2, D, acc);

    float* s0 = scratch + c2 * STR;
    float* s1 = scratch + (c2 + 1) * STR;
    if (tid >= 128) {
#pragma unroll
        for (int p = 0; p < 8; p++) {
            *(ull*)(s0 + 2 * p) = acc[p][0];
            *(ull*)(s1 + 2 * p) = acc[p][1];
        }
    }
    __syncthreads();
    if (tid < 128) {
        float* k0 = kdst + c2 * STR;
        float* k1 = kdst + (c2 + 1) * STR;
#pragma unroll
        for (int p = 0; p < 8; p++) {
            *(ull*)(k0 + 2 * p) = add2(add2(acc[p][0], *(const ull*)(s0 + 2 * p)), b2p0);
            *(ull*)(k1 + 2 * p) = add2(add2(acc[p][1], *(const ull*)(s1 + 2 * p)), b2p1);
        }
    }
}

// dst row d = ysrc row d + sum_{j<cnt} cf[j] * kT[j] row d   (thread d = tid)
__device__ __forceinline__ void combine(float* dst, const float* ysrc, const float* kbase,
                                        const float (&cf)[6], int cnt, int tid) {
    const int off = tid * STR;
    ulonglong2 e01 = *(const ulonglong2*)(ysrc + off);
    ulonglong2 e23 = *(const ulonglong2*)(ysrc + off + 4);
    ulonglong2 e45 = *(const ulonglong2*)(ysrc + off + 8);
    ulonglong2 e67 = *(const ulonglong2*)(ysrc + off + 12);
    ull e[8] = {e01.x, e01.y, e23.x, e23.y, e45.x, e45.y, e67.x, e67.y};
#pragma unroll
    for (int j = 0; j < 6; j++) {
        if (j < cnt) {
            ull c = pack2(cf[j]);
            const float* kr = kbase + j * KT_STRIDE + off;
            ulonglong2 k01 = *(const ulonglong2*)(kr);
            ulonglong2 k23 = *(const ulonglong2*)(kr + 4);
            ulonglong2 k45 = *(const ulonglong2*)(kr + 8);
            ulonglong2 k67 = *(const ulonglong2*)(kr + 12);
            e[0] = fma2(c, k01.x, e[0]); e[1] = fma2(c, k01.y, e[1]);
            e[2] = fma2(c, k23.x, e[2]); e[3] = fma2(c, k23.y, e[3]);
            e[4] = fma2(c, k45.x, e[4]); e[5] = fma2(c, k45.y, e[5]);
            e[6] = fma2(c, k67.x, e[6]); e[7] = fma2(c, k67.y, e[7]);
        }
    }
    ulonglong2 o;
    o.x = e[0]; o.y = e[1]; *(ulonglong2*)(dst + off)      = o;
    o.x = e[2]; o.y = e[3]; *(ulonglong2*)(dst + off + 4)  = o;
    o.x = e[4]; o.y = e[5]; *(ulonglong2*)(dst + off + 8)  = o;
    o.x = e[6]; o.y = e[7]; *(ulonglong2*)(dst + off + 12) = o;
}

__global__ void __launch_bounds__(THREADS, 1)
node_ode_kernel(const float* __restrict__ x0, const float* __restrict__ t,
                const float* __restrict__ W1, const float* __restrict__ b1,
                const float* __restrict__ W2, const float* __restrict__ b2,
                const float* __restrict__ Wc1, const float* __restrict__ bc1,
                const float* __restrict__ Wc2, const float* __restrict__ bc2,
                float* __restrict__ out) {
    extern __shared__ float sm[];
    float* yT  = sm + OFF_YT;
    float* ysT = sm + OFF_YST;   // GEMM1 stage input / GEMM2 reduction scratch
    float* hT  = sm + OFF_HT;
    float* kT  = sm + OFF_KT;

    const int tid   = threadIdx.x;
    const int c0    = 2 * tid;            // GEMM1 cols
    const int c2    = 2 * (tid & 127);    // GEMM2 cols
    const int khalf = tid >> 7;           // GEMM2 K-half
    const int rowBase = blockIdx.x * ROWS;

    // transpose x0 tile into yT[k][row], stride STR
    {
        const int d = tid;
#pragma unroll
        for (int r = 0; r < ROWS; r++)
            yT[d * STR + r] = x0[(size_t)(rowBase + r) * D + d];
    }

    const float2 b1v = *(const float2*)(b1 + c0);
    const ull b2p0 = pack2(b2[c2]);
    const ull b2p1 = pack2(b2[c2 + 1]);

    float tv[TPTS];
#pragma unroll
    for (int i = 0; i < TPTS; i++) tv[i] = t[i];

    __syncthreads();

    // dopri5 tableau
    const float A1[1] = {0.2f};
    const float A2[2] = {3.0f/40.0f, 9.0f/40.0f};
    const float A3[3] = {44.0f/45.0f, -56.0f/15.0f, 32.0f/9.0f};
    const float A4[4] = {19372.0f/6561.0f, -25360.0f/2187.0f, 64448.0f/6561.0f, -212.0f/729.0f};
    const float A5[5] = {9017.0f/3168.0f, -355.0f/33.0f, 46732.0f/5247.0f, 49.0f/176.0f, -5103.0f/18656.0f};
    const float B6[6] = {35.0f/384.0f, 0.0f, 500.0f/1113.0f, 125.0f/192.0f, -2187.0f/6784.0f, 11.0f/84.0f};
    const float* Arows[5] = {A1, A2, A3, A4, A5};

#pragma unroll 1
    for (int iv = 0; iv < TPTS - 1; iv++) {
        const float dt = (tv[iv + 1] - tv[iv]) * 0.25f;   // SUBSTEPS = 4
#pragma unroll 1
        for (int ss = 0; ss < 4; ss++) {
            // stage 1: k1 = f(y)
            gemm1(yT, W1, hT, b1v, c0);
            __syncthreads();
            gemm2(hT, W2, ysT, kT, b2p0, b2p1, c2, khalf, tid);
            __syncthreads();
            // stages 2..6
#pragma unroll 1
            for (int s = 1; s < 6; s++) {
                float cf[6];
#pragma unroll
                for (int j = 0; j < 6; j++) cf[j] = (j < s) ? dt * Arows[s - 1][j] : 0.0f;
                combine(ysT, yT, kT, cf, s, tid);
                __syncthreads();
                gemm1(ysT, W1, hT, b1v, c0);
                __syncthreads();
                gemm2(hT, W2, ysT, kT + s * KT_STRIDE, b2p0, b2p1, c2, khalf, tid);
                __syncthreads();
            }
            // final update: y += dt * sum b_i k_i
            float cf[6];
#pragma unroll
            for (int j = 0; j < 6; j++) cf[j] = dt * B6[j];
            combine(yT, yT, kT, cf, 6, tid);
            __syncthreads();
        }
    }

    // classifier head: h2 = relu(y @ Wc1 + bc1) -> reuse hT as [16 x 64]
    {
        const int r  = tid >> 4;
        const int cc = (tid & 15) * 4;
        float4 bb = *(const float4*)(bc1 + cc);
        float a0 = bb.x, a1 = bb.y, a2 = bb.z, a3 = bb.w;
#pragma unroll 4
        for (int k = 0; k < D; k++) {
            float a = yT[k * STR + r];
            float4 w = *(const float4*)(Wc1 + k * 64 + cc);
            a0 = fmaf(a, w.x, a0); a1 = fmaf(a, w.y, a1);
            a2 = fmaf(a, w.z, a2); a3 = fmaf(a, w.w, a3);
        }
        float4 o;
        o.x = fmaxf(a0, 0.0f); o.y = fmaxf(a1, 0.0f);
        o.z = fmaxf(a2, 0.0f); o.w = fmaxf(a3, 0.0f);
        *(float4*)(hT + r * 64 + cc) = o;
    }
    __syncthreads();
    // logits = h2 @ Wc2 + bc2, [16 x 10]
    if (tid < ROWS * NCLS) {
        const int r = tid / NCLS;
        const int c = tid - r * NCLS;
        float s = bc2[c];
#pragma unroll 8
        for (int k = 0; k < 64; k++)
            s = fmaf(hT[r * 64 + k], Wc2[k * NCLS + c], s);
        out[(size_t)(rowBase + r) * NCLS + c] = s;
    }
}

extern "C" void kernel_launch(void* const* d_in, const int* in_sizes, int n_in,
                              void* d_out, int out_size) {
    const float* x0  = (const float*)d_in[0];
    const float* t   = (const float*)d_in[1];
    const float* W1  = (const float*)d_in[2];
    const float* b1  = (const float*)d_in[3];
    const float* W2  = (const float*)d_in[4];
    const float* b2  = (const float*)d_in[5];
    const float* Wc1 = (const float*)d_in[6];
    const float* bc1 = (const float*)d_in[7];
    const float* Wc2 = (const float*)d_in[8];
    const float* bc2 = (const float*)d_in[9];
    float* out = (float*)d_out;

    static bool attr_set = false;
    if (!attr_set) {
        cudaFuncSetAttribute(node_ode_kernel,
                             cudaFuncAttributeMaxDynamicSharedMemorySize, SMEM_BYTES);
        attr_set = true;
    }
    node_ode_kernel<<<2048 / ROWS, THREADS, SMEM_BYTES>>>(
        x0, t, W1, b1, W2, b2, Wc1, bc1, Wc2, bc2, out);
}

// round 10
// speedup vs baseline: 1.0924x; 1.0924x over previous
#include <cuda_runtime.h>
#include <cstdint>

using ull = unsigned long long;

static constexpr int D = 256, H = 512, NCLS = 10, TPTS = 8;
static constexpr int ROWS = 16, THREADS = 256;
static constexpr int STR = 20;                 // padded floats per transposed row (16 used)
// smem layout (floats)
static constexpr int OFF_YT  = 0;              // 256*20
static constexpr int OFF_YST = 256 * STR;      // 5120  (stage input / GEMM2 reduction scratch)
static constexpr int OFF_HT  = OFF_YST + 256 * STR;   // 10240
static constexpr int OFF_KT  = OFF_HT + 512 * STR;    // 20480
static constexpr int KT_STRIDE = 256 * STR;    // 5120 floats per k-stage
static constexpr int SMEM_FLOATS = OFF_KT + 6 * KT_STRIDE;   // 51200
static constexpr int SMEM_BYTES  = SMEM_FLOATS * 4;          // 204800

__device__ __forceinline__ ull fma2(ull a, ull b, ull c) {
    ull d; asm("fma.rn.f32x2 %0, %1, %2, %3;" : "=l"(d) : "l"(a), "l"(b), "l"(c)); return d;
}
__device__ __forceinline__ ull add2(ull a, ull b) {
    ull d; asm("add.rn.f32x2 %0, %1, %2;" : "=l"(d) : "l"(a), "l"(b)); return d;
}
__device__ __forceinline__ ull pack2(float x) {
    ull r; asm("mov.b64 %0, {%1, %1};" : "=l"(r) : "f"(x)); return r;
}
__device__ __forceinline__ float2 u2f(ull v) {
    float2 r; asm("mov.b64 {%0, %1}, %2;" : "=f"(r.x), "=f"(r.y) : "l"(v)); return r;
}
__device__ __forceinline__ float tanhfast(float x) {
    float e = __expf(2.0f * x);
    return 1.0f - __fdividef(2.0f, e + 1.0f);
}

// one 8-k block: R=8 rows (4 packed pairs), C=4 cols. acts at actT (+j*STR),
// weights preloaded in w[8] (float4 = 4 cols).
__device__ __forceinline__ void gblock8(const float* actT, const float4* w, ull (&acc)[4][4]) {
#pragma unroll
    for (int j = 0; j < 8; j++) {
        const float* row = actT + j * STR;
        ulonglong2 a01 = *(const ulonglong2*)(row);
        ulonglong2 a23 = *(const ulonglong2*)(row + 4);
        ull a[4] = {a01.x, a01.y, a23.x, a23.y};
        float4 wv = w[j];
        ull b0 = pack2(wv.x), b1 = pack2(wv.y), b2 = pack2(wv.z), b3 = pack2(wv.w);
#pragma unroll
        for (int p = 0; p < 4; p++) {
            acc[p][0] = fma2(a[p], b0, acc[p][0]);
            acc[p][1] = fma2(a[p], b1, acc[p][1]);
            acc[p][2] = fma2(a[p], b2, acc[p][2]);
            acc[p][3] = fma2(a[p], b3, acc[p][3]);
        }
    }
}

// K = 256 k's; weights from gmem, row stride ws, 4 consecutive cols per LDG.128.
__device__ __forceinline__ void gloop(const float* actT, const float* wp, int ws,
                                      ull (&acc)[4][4]) {
    float4 wA[8], wB[8];
#pragma unroll
    for (int j = 0; j < 8; j++) wA[j] = *(const float4*)(wp + j * ws);
#pragma unroll 1
    for (int kb = 0; kb < 32; kb += 2) {
        const float* wpn = wp + (kb + 1) * 8 * ws;
#pragma unroll
        for (int j = 0; j < 8; j++) wB[j] = *(const float4*)(wpn + j * ws);
        gblock8(actT + kb * 8 * STR, wA, acc);
        if (kb + 2 < 32) {
            const float* wpn2 = wp + (kb + 2) * 8 * ws;
#pragma unroll
            for (int j = 0; j < 8; j++) wA[j] = *(const float4*)(wpn2 + j * ws);
        }
        gblock8(actT + (kb + 1) * 8 * STR, wB, acc);
    }
}

// GEMM1: hT = tanh(actT^T @ W1 + b1). thread: rows rg*8..+8, cols c0..c0+3, K=256.
__device__ __forceinline__ void gemm1(const float* actT, const float* W1g, float* hT,
                                      float4 b1v, int rg, int c0) {
    ull acc[4][4];
#pragma unroll
    for (int p = 0; p < 4; p++)
#pragma unroll
        for (int q = 0; q < 4; q++) acc[p][q] = 0ULL;
    gloop(actT + rg * 8, W1g + c0, H, acc);
    const float bq[4] = {b1v.x, b1v.y, b1v.z, b1v.w};
#pragma unroll
    for (int q = 0; q < 4; q++) {
        float2 f0 = u2f(acc[0][q]), f1 = u2f(acc[1][q]);
        float2 f2 = u2f(acc[2][q]), f3 = u2f(acc[3][q]);
        float4 v0, v1;
        v0.x = tanhfast(f0.x + bq[q]); v0.y = tanhfast(f0.y + bq[q]);
        v0.z = tanhfast(f1.x + bq[q]); v0.w = tanhfast(f1.y + bq[q]);
        v1.x = tanhfast(f2.x + bq[q]); v1.y = tanhfast(f2.y + bq[q]);
        v1.z = tanhfast(f3.x + bq[q]); v1.w = tanhfast(f3.y + bq[q]);
        float* hc = hT + (c0 + q) * STR + rg * 8;
        *(float4*)(hc)     = v0;
        *(float4*)(hc + 4) = v1;
    }
}

// GEMM2: kdst = hT^T @ W2 + b2. thread: rows rg2*8..+8, cols c2..c2+3, K-half kh.
// 2-way K reduction via scratch (kh1 writes partials, kh0 adds + bias + stores).
__device__ __forceinline__ void gemm2(const float* hT, const float* W2g, float* scratch,
                                      float* kdst, const ull (&b2p)[4],
                                      int rg2, int kh, int c2) {
    ull acc[4][4];
#pragma unroll
    for (int p = 0; p < 4; p++)
#pragma unroll
        for (int q = 0; q < 4; q++) acc[p][q] = 0ULL;
    gloop(hT + kh * 256 * STR + rg2 * 8, W2g + (size_t)kh * 256 * D + c2, D, acc);

    if (kh == 1) {
#pragma unroll
        for (int q = 0; q < 4; q++) {
            float* sc = scratch + (c2 + q) * STR + rg2 * 8;
            ulonglong2 o;
            o.x = acc[0][q]; o.y = acc[1][q]; *(ulonglong2*)(sc)     = o;
            o.x = acc[2][q]; o.y = acc[3][q]; *(ulonglong2*)(sc + 4) = o;
        }
    }
    __syncthreads();
    if (kh == 0) {
#pragma unroll
        for (int q = 0; q < 4; q++) {
            const float* sc = scratch + (c2 + q) * STR + rg2 * 8;
            float* kc = kdst + (c2 + q) * STR + rg2 * 8;
            ulonglong2 s01 = *(const ulonglong2*)(sc);
            ulonglong2 s23 = *(const ulonglong2*)(sc + 4);
            ulonglong2 o;
            o.x = add2(add2(acc[0][q], s01.x), b2p[q]);
            o.y = add2(add2(acc[1][q], s01.y), b2p[q]);
            *(ulonglong2*)(kc) = o;
            o.x = add2(add2(acc[2][q], s23.x), b2p[q]);
            o.y = add2(add2(acc[3][q], s23.y), b2p[q]);
            *(ulonglong2*)(kc + 4) = o;
        }
    }
}

// dst col d = ysrc col d + sum_{j<cnt} cf[j] * kT[j] col d   (thread d = tid)
__device__ __forceinline__ void combine(float* dst, const float* ysrc, const float* kbase,
                                        const float (&cf)[6], int cnt, int tid) {
    const int off = tid * STR;
    ulonglong2 e01 = *(const ulonglong2*)(ysrc + off);
    ulonglong2 e23 = *(const ulonglong2*)(ysrc + off + 4);
    ulonglong2 e45 = *(const ulonglong2*)(ysrc + off + 8);
    ulonglong2 e67 = *(const ulonglong2*)(ysrc + off + 12);
    ull e[8] = {e01.x, e01.y, e23.x, e23.y, e45.x, e45.y, e67.x, e67.y};
#pragma unroll
    for (int j = 0; j < 6; j++) {
        if (j < cnt) {
            ull c = pack2(cf[j]);
            const float* kr = kbase + j * KT_STRIDE + off;
            ulonglong2 k01 = *(const ulonglong2*)(kr);
            ulonglong2 k23 = *(const ulonglong2*)(kr + 4);
            ulonglong2 k45 = *(const ulonglong2*)(kr + 8);
            ulonglong2 k67 = *(const ulonglong2*)(kr + 12);
            e[0] = fma2(c, k01.x, e[0]); e[1] = fma2(c, k01.y, e[1]);
            e[2] = fma2(c, k23.x, e[2]); e[3] = fma2(c, k23.y, e[3]);
            e[4] = fma2(c, k45.x, e[4]); e[5] = fma2(c, k45.y, e[5]);
            e[6] = fma2(c, k67.x, e[6]); e[7] = fma2(c, k67.y, e[7]);
        }
    }
    ulonglong2 o;
    o.x = e[0]; o.y = e[1]; *(ulonglong2*)(dst + off)      = o;
    o.x = e[2]; o.y = e[3]; *(ulonglong2*)(dst + off + 4)  = o;
    o.x = e[4]; o.y = e[5]; *(ulonglong2*)(dst + off + 8)  = o;
    o.x = e[6]; o.y = e[7]; *(ulonglong2*)(dst + off + 12) = o;
}

__global__ void __launch_bounds__(THREADS, 1)
node_ode_kernel(const float* __restrict__ x0, const float* __restrict__ t,
                const float* __restrict__ W1, const float* __restrict__ b1,
                const float* __restrict__ W2, const float* __restrict__ b2,
                const float* __restrict__ Wc1, const float* __restrict__ bc1,
                const float* __restrict__ Wc2, const float* __restrict__ bc2,
                float* __restrict__ out) {
    extern __shared__ float sm[];
    float* yT  = sm + OFF_YT;
    float* ysT = sm + OFF_YST;   // stage input / GEMM2 reduction scratch
    float* hT  = sm + OFF_HT;
    float* kT  = sm + OFF_KT;

    const int tid = threadIdx.x;
    const int rg  = tid >> 7;             // GEMM1 row-group
    const int c0  = (tid & 127) * 4;      // GEMM1 cols
    const int rg2 = (tid >> 6) & 1;       // GEMM2 row-group
    const int kh  = tid >> 7;             // GEMM2 K-half
    const int c2  = (tid & 63) * 4;       // GEMM2 cols
    const int rowBase = blockIdx.x * ROWS;

    // transpose x0 tile into yT[k][row]
    {
        const int d = tid;
#pragma unroll
        for (int r = 0; r < ROWS; r++)
            yT[d * STR + r] = x0[(size_t)(rowBase + r) * D + d];
    }

    const float4 b1v = *(const float4*)(b1 + c0);
    ull b2p[4];
#pragma unroll
    for (int q = 0; q < 4; q++) b2p[q] = pack2(b2[c2 + q]);

    float tv[TPTS];
#pragma unroll
    for (int i = 0; i < TPTS; i++) tv[i] = t[i];

    __syncthreads();

    // dopri5 tableau
    const float A1[1] = {0.2f};
    const float A2[2] = {3.0f/40.0f, 9.0f/40.0f};
    const float A3[3] = {44.0f/45.0f, -56.0f/15.0f, 32.0f/9.0f};
    const float A4[4] = {19372.0f/6561.0f, -25360.0f/2187.0f, 64448.0f/6561.0f, -212.0f/729.0f};
    const float A5[5] = {9017.0f/3168.0f, -355.0f/33.0f, 46732.0f/5247.0f, 49.0f/176.0f, -5103.0f/18656.0f};
    const float B6[6] = {35.0f/384.0f, 0.0f, 500.0f/1113.0f, 125.0f/192.0f, -2187.0f/6784.0f, 11.0f/84.0f};
    const float* Arows[5] = {A1, A2, A3, A4, A5};

#pragma unroll 1
    for (int iv = 0; iv < TPTS - 1; iv++) {
        const float dt = (tv[iv + 1] - tv[iv]) * 0.25f;   // SUBSTEPS = 4
#pragma unroll 1
        for (int ss = 0; ss < 4; ss++) {
            // stage 1: k1 = f(y)
            gemm1(yT, W1, hT, b1v, rg, c0);
            __syncthreads();
            gemm2(hT, W2, ysT, kT, b2p, rg2, kh, c2);
            __syncthreads();
            // stages 2..6
#pragma unroll 1
            for (int s = 1; s < 6; s++) {
                float cf[6];
#pragma unroll
                for (int j = 0; j < 6; j++) cf[j] = (j < s) ? dt * Arows[s - 1][j] : 0.0f;
                combine(ysT, yT, kT, cf, s, tid);
                __syncthreads();
                gemm1(ysT, W1, hT, b1v, rg, c0);
                __syncthreads();
                gemm2(hT, W2, ysT, kT + s * KT_STRIDE, b2p, rg2, kh, c2);
                __syncthreads();
            }
            // final update: y += dt * sum b_i k_i
            float cf[6];
#pragma unroll
            for (int j = 0; j < 6; j++) cf[j] = dt * B6[j];
            combine(yT, yT, kT, cf, 6, tid);
            __syncthreads();
        }
    }

    // classifier head: h2 = relu(y @ Wc1 + bc1) -> reuse hT as [16 x 64]
    {
        const int r  = tid >> 4;
        const int cc = (tid & 15) * 4;
        float4 bb = *(const float4*)(bc1 + cc);
        float a0 = bb.x, a1 = bb.y, a2 = bb.z, a3 = bb.w;
#pragma unroll 4
        for (int k = 0; k < D; k++) {
            float a = yT[k * STR + r];
            float4 w = *(const float4*)(Wc1 + k * 64 + cc);
            a0 = fmaf(a, w.x, a0); a1 = fmaf(a, w.y, a1);
            a2 = fmaf(a, w.z, a2); a3 = fmaf(a, w.w, a3);
        }
        float4 o;
        o.x = fmaxf(a0, 0.0f); o.y = fmaxf(a1, 0.0f);
        o.z = fmaxf(a2, 0.0f); o.w = fmaxf(a3, 0.0f);
        *(float4*)(hT + r * 64 + cc) = o;
    }
    __syncthreads();
    // logits = h2 @ Wc2 + bc2, [16 x 10]
    if (tid < ROWS * NCLS) {
        const int r = tid / NCLS;
        const int c = tid - r * NCLS;
        float s = bc2[c];
#pragma unroll 8
        for (int k = 0; k < 64; k++)
            s = fmaf(hT[r * 64 + k], Wc2[k * NCLS + c], s);
        out[(size_t)(rowBase + r) * NCLS + c] = s;
    }
}

extern "C" void kernel_launch(void* const* d_in, const int* in_sizes, int n_in,
                              void* d_out, int out_size) {
    const float* x0  = (const float*)d_in[0];
    const float* t   = (const float*)d_in[1];
    const float* W1  = (const float*)d_in[2];
    const float* b1  = (const float*)d_in[3];
    const float* W2  = (const float*)d_in[4];
    const float* b2  = (const float*)d_in[5];
    const float* Wc1 = (const float*)d_in[6];
    const float* bc1 = (const float*)d_in[7];
    const float* Wc2 = (const float*)d_in[8];
    const float* bc2 = (const float*)d_in[9];
    float* out = (float*)d_out;

    static bool attr_set = false;
    if (!attr_set) {
        cudaFuncSetAttribute(node_ode_kernel,
                             cudaFuncAttributeMaxDynamicSharedMemorySize, SMEM_BYTES);
        attr_set = true;
    }
    node_ode_kernel<<<2048 / ROWS, THREADS, SMEM_BYTES>>>(
        x0, t, W1, b1, W2, b2, Wc1, bc1, Wc2, bc2, out);
}